// round 2
// baseline (speedup 1.0000x reference)
#include <cuda_runtime.h>

// Problem constants
#define BB 256      // batch
#define RR 1152     // routes
#define CC 10       // caps
#define DD 16       // d_out
#define II 8        // d_in
#define NN 160      // CC*DD

// GEMM tiling
#define BT 32            // batch tile per block
#define RCHUNK 64        // routes per block (K split)
#define NKB 18           // RR / RCHUNK
#define NBT 8            // BB / BT

typedef unsigned long long u64;

// Scratch (static device arrays; no allocation anywhere)
__device__ float g_wsum[RR * CC * II];        // sum_d W[r,c,d,i]
__device__ float g_t[CC * BB * RR];           // t[c][b][r] = sum_d u_hat
__device__ float g_spart[NKB * BB * NN];      // per-K-chunk partial s
__device__ float g_v[BB * NN];                // squashed v
__device__ float g_bij[RR * NN];              // routing logits
__device__ float g_c[RR * NN];                // softmax(b) over r

// ---- packed f32x2 helpers (FFMA2 path on sm_103a) ----
__device__ __forceinline__ u64 pack2(float lo, float hi) {
    u64 r;
    asm("mov.b64 %0, {%1, %2};" : "=l"(r) : "f"(lo), "f"(hi));
    return r;
}
__device__ __forceinline__ float lo2(u64 v) { return __uint_as_float((unsigned int)v); }
__device__ __forceinline__ float hi2(u64 v) { return __uint_as_float((unsigned int)(v >> 32)); }
__device__ __forceinline__ void fma2(u64& d, u64 a, u64 b) {
    asm("fma.rn.f32x2 %0, %1, %2, %0;" : "+l"(d) : "l"(a), "l"(b));
}

// ---------------------------------------------------------------------------
// Wsum[r,c,i] = sum_d W[r,c,d,i]
// ---------------------------------------------------------------------------
__global__ void wsum_kernel(const float* __restrict__ W) {
    int id = blockIdx.x * blockDim.x + threadIdx.x;   // over RR*CC*II
    if (id >= RR * CC * II) return;
    int rc = id / II, i = id - rc * II;
    const float* p = W + rc * DD * II + i;
    float s = 0.f;
    #pragma unroll
    for (int d = 0; d < DD; d++) s += p[d * II];
    g_wsum[id] = s;
}

// ---------------------------------------------------------------------------
// t[c][b][r] = sum_i Wsum[r,c,i] * u[b,r,i]   (iteration-invariant)
// grid (RR/128, BB), 128 threads
// ---------------------------------------------------------------------------
__global__ void t_kernel(const float* __restrict__ u) {
    int r = blockIdx.x * 128 + threadIdx.x;
    int b = blockIdx.y;
    const float4* up = (const float4*)(u + (b * RR + r) * II);
    float4 ua = up[0], ub = up[1];
    float uu[8] = {ua.x, ua.y, ua.z, ua.w, ub.x, ub.y, ub.z, ub.w};
    #pragma unroll
    for (int c = 0; c < CC; c++) {
        const float* wp = g_wsum + (r * CC + c) * II;
        float s = 0.f;
        #pragma unroll
        for (int i = 0; i < II; i++) s += wp[i] * uu[i];
        g_t[(c * BB + b) * RR + r] = s;   // coalesced over r
    }
}

// ---------------------------------------------------------------------------
// s_part[kb][b][n] = sum_{r in chunk kb} c[r,n] * sum_i W[r,n,i]*u[b,r,i]
// FFMA2 paired over i (even/odd partials, horizontal add at write).
// grid (NBT, NKB), 256 threads; thread = (ty,tx): 4 b's x 5 n's.
// ---------------------------------------------------------------------------
__global__ __launch_bounds__(256) void gemm_kernel(
    const float* __restrict__ u, const float* __restrict__ W,
    int use_c, float cuni)
{
    __shared__ u64 u_s[4][BT][4];   // [rs][m][ip]  (u[b,r,2ip], u[b,r,2ip+1])
    __shared__ u64 w_s[4][4][NN];   // [rs][ip][n]  (c*W[..,2ip], c*W[..,2ip+1])

    const int tid = threadIdx.x;
    const int tx = tid & 31, ty = tid >> 5;
    const int bt = blockIdx.x, kb = blockIdx.y;
    const int r0 = kb * RCHUNK;

    const u64 z = pack2(0.f, 0.f);
    u64 acc[4][5];
    #pragma unroll
    for (int jm = 0; jm < 4; jm++)
        #pragma unroll
        for (int jn = 0; jn < 5; jn++) acc[jm][jn] = z;

    const int sbl = tid & 31;
    const int srs = (tid >> 5) & 3;
    const int shalf = tid >> 7;

    for (int st = 0; st < RCHUNK / 4; st++) {
        const int rb = r0 + st * 4;
        // stage u tile: 32 b x 4 r x 8 i (256 float4, one per thread)
        {
            const float4 v4 = *(const float4*)(
                u + ((bt * BT + sbl) * RR + rb + srs) * II + shalf * 4);
            u_s[srs][sbl][shalf * 2 + 0] = pack2(v4.x, v4.y);
            u_s[srs][sbl][shalf * 2 + 1] = pack2(v4.z, v4.w);
        }
        // stage W tile with c_ij folded in: 4 r x 160 n x 8 i (1280 float4, 5/thread)
        #pragma unroll
        for (int k = 0; k < 5; k++) {
            int idx = tid + 256 * k;          // 0..1279
            int rs = idx / 320;
            int rem = idx - rs * 320;
            int n = rem >> 1, iq = rem & 1;
            int r = rb + rs;
            float cv = use_c ? g_c[r * NN + n] : cuni;
            const float4 w4 = *(const float4*)(W + (r * NN + n) * II + iq * 4);
            w_s[rs][iq * 2 + 0][n] = pack2(w4.x * cv, w4.y * cv);
            w_s[rs][iq * 2 + 1][n] = pack2(w4.z * cv, w4.w * cv);
        }
        __syncthreads();

        #pragma unroll
        for (int rs = 0; rs < 4; rs++) {
            #pragma unroll
            for (int ip = 0; ip < 4; ip++) {
                u64 uu[4], ww[5];
                #pragma unroll
                for (int jm = 0; jm < 4; jm++) uu[jm] = u_s[rs][ty * 4 + jm][ip];
                #pragma unroll
                for (int jn = 0; jn < 5; jn++) ww[jn] = w_s[rs][ip][tx + 32 * jn];
                #pragma unroll
                for (int jm = 0; jm < 4; jm++)
                    #pragma unroll
                    for (int jn = 0; jn < 5; jn++)
                        fma2(acc[jm][jn], uu[jm], ww[jn]);
            }
        }
        __syncthreads();
    }

    #pragma unroll
    for (int jm = 0; jm < 4; jm++) {
        int b = bt * BT + ty * 4 + jm;
        #pragma unroll
        for (int jn = 0; jn < 5; jn++) {
            int n = tx + 32 * jn;
            g_spart[(kb * BB + b) * NN + n] = lo2(acc[jm][jn]) + hi2(acc[jm][jn]);
        }
    }
}

// ---------------------------------------------------------------------------
// Reduce K-chunk partials, squash, write v (and final output).
// grid BB*NN/256, 256 threads
// ---------------------------------------------------------------------------
__global__ void reduce_squash_kernel(float* __restrict__ dout) {
    int idx = blockIdx.x * 256 + threadIdx.x;   // b*NN + n
    float s = 0.f;
    #pragma unroll
    for (int kb = 0; kb < NKB; kb++) s += g_spart[kb * BB * NN + idx];
    float sq = s * s;
    float out = sq / (1.f + sq) * s / (sqrtf(sq) + 1e-5f);
    g_v[idx] = out;
    dout[idx] = out;
}

// ---------------------------------------------------------------------------
// b_ij[r, c*16+d] += (1/B) sum_b t[c][b][r] * v[b, c*16+d]
// grid (RR/128, CC), 128 threads (one r per thread)
// ---------------------------------------------------------------------------
__global__ void update_kernel(int first) {
    __shared__ u64 v_s[BB][DD / 2];   // v_c, d paired: 16 KB
    const int c = blockIdx.y;
    const int r = blockIdx.x * 128 + threadIdx.x;

    // stage v[:, c, :] — 1024 float4, 8 per thread
    #pragma unroll
    for (int k = 0; k < 8; k++) {
        int idx = threadIdx.x + 128 * k;   // 0..1023
        int b = idx >> 2, q = idx & 3;
        const float4 v4 = *(const float4*)(g_v + b * NN + c * DD + q * 4);
        v_s[b][q * 2 + 0] = pack2(v4.x, v4.y);
        v_s[b][q * 2 + 1] = pack2(v4.z, v4.w);
    }
    __syncthreads();

    const u64 z = pack2(0.f, 0.f);
    u64 acc[8];
    #pragma unroll
    for (int j = 0; j < 8; j++) acc[j] = z;

    const float* tp = g_t + (c * BB) * RR + r;
    for (int b0 = 0; b0 < BB; b0 += 8) {
        float tv[8];
        #pragma unroll
        for (int q = 0; q < 8; q++) tv[q] = tp[(b0 + q) * RR];
        #pragma unroll
        for (int q = 0; q < 8; q++) {
            u64 t2 = pack2(tv[q], tv[q]);
            #pragma unroll
            for (int j = 0; j < 8; j++) fma2(acc[j], t2, v_s[b0 + q][j]);
        }
    }

    const float inv = 1.f / (float)BB;
    #pragma unroll
    for (int j = 0; j < 8; j++) {
        float x = lo2(acc[j]) * inv;
        float y = hi2(acc[j]) * inv;
        int o = r * NN + c * DD + 2 * j;
        if (!first) {
            float2 old = *(const float2*)(g_bij + o);
            x += old.x; y += old.y;
        }
        *(float2*)(g_bij + o) = make_float2(x, y);
    }
}

// ---------------------------------------------------------------------------
// c[r,n] = softmax over r of b_ij[r,n].  grid NN blocks, 128 threads.
// ---------------------------------------------------------------------------
__global__ void softmax_kernel() {
    __shared__ float red[128];
    const int n = blockIdx.x;
    const int tid = threadIdx.x;

    float vals[9];
    #pragma unroll
    for (int j = 0; j < 9; j++) vals[j] = g_bij[(tid + 128 * j) * NN + n];

    float m = vals[0];
    #pragma unroll
    for (int j = 1; j < 9; j++) m = fmaxf(m, vals[j]);
    red[tid] = m;
    __syncthreads();
    for (int s = 64; s > 0; s >>= 1) {
        if (tid < s) red[tid] = fmaxf(red[tid], red[tid + s]);
        __syncthreads();
    }
    m = red[0];
    __syncthreads();

    float e[9];
    float lsum = 0.f;
    #pragma unroll
    for (int j = 0; j < 9; j++) { e[j] = expf(vals[j] - m); lsum += e[j]; }
    red[tid] = lsum;
    __syncthreads();
    for (int s = 64; s > 0; s >>= 1) {
        if (tid < s) red[tid] += red[tid + s];
        __syncthreads();
    }
    float inv = 1.f / red[0];

    #pragma unroll
    for (int j = 0; j < 9; j++)
        g_c[(tid + 128 * j) * NN + n] = e[j] * inv;
}

// ---------------------------------------------------------------------------
extern "C" void kernel_launch(void* const* d_in, const int* in_sizes, int n_in,
                              void* d_out, int out_size) {
    const float* u = (const float*)d_in[0];   // (B, R, 8)
    const float* W = (const float*)d_in[1];   // (R, C, 16, 8)
    float* out = (float*)d_out;               // (B, C, 16) = 40960 floats

    // Precompute (iteration-invariant)
    wsum_kernel<<<(RR * CC * II + 255) / 256, 256>>>(W);
    t_kernel<<<dim3(RR / 128, BB), 128>>>(u);

    // Iteration 0: c_ij uniform = 1/R
    gemm_kernel<<<dim3(NBT, NKB), 256>>>(u, W, 0, 1.0f / (float)RR);
    reduce_squash_kernel<<<BB * NN / 256, 256>>>(out);
    update_kernel<<<dim3(RR / 128, CC), 128>>>(1);
    softmax_kernel<<<NN, 128>>>();

    // Iteration 1
    gemm_kernel<<<dim3(NBT, NKB), 256>>>(u, W, 1, 0.f);
    reduce_squash_kernel<<<BB * NN / 256, 256>>>(out);
    update_kernel<<<dim3(RR / 128, CC), 128>>>(0);
    softmax_kernel<<<NN, 128>>>();

    // Iteration 2 (final v -> out)
    gemm_kernel<<<dim3(NBT, NKB), 256>>>(u, W, 1, 0.f);
    reduce_squash_kernel<<<BB * NN / 256, 256>>>(out);
}

// round 6
// speedup vs baseline: 1.3872x; 1.3872x over previous
#include <cuda_runtime.h>

// Problem constants
#define BB 256      // batch
#define RR 1152     // routes
#define CC 10       // caps
#define DD 16       // d_out
#define II 8        // d_in
#define NN 160      // CC*DD

// GEMM tiling
#define BT 32            // batch tile per block
#define RCHUNK 32        // routes per block (K split)
#define NKB 36           // RR / RCHUNK
#define NBT 8            // BB / BT
#define NSTAGE (RCHUNK/4)

#define BTB 8            // batch tile in t_kernel

typedef unsigned long long u64;

// Scratch (static device arrays; no allocation anywhere)
__device__ float g_wsumT[CC * II * RR];       // [c][i][r] sum_d W[r,c,d,i]
__device__ float g_t[CC * BB * RR];           // t[c][b][r] = sum_d u_hat
__device__ float g_spart[NKB * BB * NN];      // per-K-chunk partial s
__device__ float g_v[BB * NN];                // squashed v
__device__ float g_bT[NN * RR];               // routing logits, transposed [n][r]
__device__ float g_c[RR * NN];                // softmax(b) over r, [r][n]

// ---- packed f32x2 helpers (FFMA2 path on sm_103a) ----
__device__ __forceinline__ u64 pack2(float lo, float hi) {
    u64 r;
    asm("mov.b64 %0, {%1, %2};" : "=l"(r) : "f"(lo), "f"(hi));
    return r;
}
__device__ __forceinline__ float lo2(u64 v) { return __uint_as_float((unsigned int)v); }
__device__ __forceinline__ float hi2(u64 v) { return __uint_as_float((unsigned int)(v >> 32)); }
__device__ __forceinline__ void fma2(u64& d, u64 a, u64 b) {
    asm("fma.rn.f32x2 %0, %1, %2, %0;" : "+l"(d) : "l"(a), "l"(b));
}

// ---------------------------------------------------------------------------
// wsumT[c][i][r] = sum_d W[r,c,d,i]   (coalesced reads, scattered small stores)
// ---------------------------------------------------------------------------
__global__ void wsum_kernel(const float* __restrict__ W) {
    int id = blockIdx.x * blockDim.x + threadIdx.x;   // over RR*CC*II
    if (id >= RR * CC * II) return;
    int rc = id / II, i = id - rc * II;
    int r = rc / CC, c = rc - r * CC;
    const float* p = W + rc * DD * II + i;
    float s = 0.f;
    #pragma unroll
    for (int d = 0; d < DD; d++) s += p[d * II];
    g_wsumT[(c * II + i) * RR + r] = s;
}

// ---------------------------------------------------------------------------
// t[c][b][r] = sum_i wsumT[c][i][r] * u[b,r,i]   (iteration-invariant)
// grid (RR/128, BB/BTB), 128 threads; wsum loads reused across BTB batches
// ---------------------------------------------------------------------------
__global__ __launch_bounds__(128) void t_kernel(const float* __restrict__ u) {
    const int r = blockIdx.x * 128 + threadIdx.x;
    const int b0 = blockIdx.y * BTB;

    float uu[BTB][II];
    #pragma unroll
    for (int bi = 0; bi < BTB; bi++) {
        const float4* up = (const float4*)(u + ((b0 + bi) * RR + r) * II);
        float4 a = up[0], b = up[1];
        uu[bi][0] = a.x; uu[bi][1] = a.y; uu[bi][2] = a.z; uu[bi][3] = a.w;
        uu[bi][4] = b.x; uu[bi][5] = b.y; uu[bi][6] = b.z; uu[bi][7] = b.w;
    }

    #pragma unroll
    for (int c = 0; c < CC; c++) {
        float ws[II];
        #pragma unroll
        for (int i = 0; i < II; i++) ws[i] = g_wsumT[(c * II + i) * RR + r];
        #pragma unroll
        for (int bi = 0; bi < BTB; bi++) {
            float s = 0.f;
            #pragma unroll
            for (int i = 0; i < II; i++) s += ws[i] * uu[bi][i];
            g_t[(c * BB + b0 + bi) * RR + r] = s;   // coalesced over r
        }
    }
}

// ---------------------------------------------------------------------------
// s_part[kb][b][n] = sum_{r in chunk kb} c[r,n] * sum_i W[r,n,i]*u[b,r,i]
// FFMA2 paired over i; software-pipelined staging (LDG prefetch into regs).
// grid (NBT, NKB), 256 threads; thread = (ty,tx): 4 b's x 5 n's.
// ---------------------------------------------------------------------------
__global__ __launch_bounds__(256, 2) void gemm_kernel(
    const float* __restrict__ u, const float* __restrict__ W,
    int use_c, float cuni)
{
    __shared__ u64 u_s[4][BT][4];   // [rs][m][ip]
    __shared__ u64 w_s[4][4][NN];   // [rs][ip][n]

    const int tid = threadIdx.x;
    const int tx = tid & 31, ty = tid >> 5;
    const int bt = blockIdx.x, kb = blockIdx.y;
    const int r0 = kb * RCHUNK;

    const u64 z = pack2(0.f, 0.f);
    u64 acc[4][5];
    #pragma unroll
    for (int jm = 0; jm < 4; jm++)
        #pragma unroll
        for (int jn = 0; jn < 5; jn++) acc[jm][jn] = z;

    // staging index decomposition (stage-invariant)
    const int sbl = tid & 31;
    const int srs = (tid >> 5) & 3;
    const int shalf = tid >> 7;
    int wrs[5], wn[5], wiq[5];
    #pragma unroll
    for (int k = 0; k < 5; k++) {
        int idx = tid + 256 * k;          // 0..1279
        wrs[k] = idx / 320;
        int rem = idx - wrs[k] * 320;
        wn[k] = rem >> 1;
        wiq[k] = rem & 1;
    }

    // prefetch registers
    float4 pu;
    float4 pw[5];
    float  pc[5];

    // prologue: prefetch stage 0
    {
        pu = *(const float4*)(u + ((bt * BT + sbl) * RR + r0 + srs) * II + shalf * 4);
        #pragma unroll
        for (int k = 0; k < 5; k++) {
            int r = r0 + wrs[k];
            pc[k] = use_c ? g_c[r * NN + wn[k]] : cuni;
            pw[k] = *(const float4*)(W + (r * NN + wn[k]) * II + wiq[k] * 4);
        }
    }

    for (int st = 0; st < NSTAGE; st++) {
        if (st) __syncthreads();          // prev compute done reading smem

        // commit prefetched tile to smem (fold c into W)
        u_s[srs][sbl][shalf * 2 + 0] = pack2(pu.x, pu.y);
        u_s[srs][sbl][shalf * 2 + 1] = pack2(pu.z, pu.w);
        #pragma unroll
        for (int k = 0; k < 5; k++) {
            w_s[wrs[k]][wiq[k] * 2 + 0][wn[k]] = pack2(pw[k].x * pc[k], pw[k].y * pc[k]);
            w_s[wrs[k]][wiq[k] * 2 + 1][wn[k]] = pack2(pw[k].z * pc[k], pw[k].w * pc[k]);
        }

        // prefetch next stage (overlaps with compute below)
        if (st < NSTAGE - 1) {
            const int rb = r0 + (st + 1) * 4;
            pu = *(const float4*)(u + ((bt * BT + sbl) * RR + rb + srs) * II + shalf * 4);
            #pragma unroll
            for (int k = 0; k < 5; k++) {
                int r = rb + wrs[k];
                pc[k] = use_c ? g_c[r * NN + wn[k]] : cuni;
                pw[k] = *(const float4*)(W + (r * NN + wn[k]) * II + wiq[k] * 4);
            }
        }
        __syncthreads();

        #pragma unroll
        for (int rs = 0; rs < 4; rs++) {
            #pragma unroll
            for (int ip = 0; ip < 4; ip++) {
                u64 uu[4], ww[5];
                #pragma unroll
                for (int jm = 0; jm < 4; jm++) uu[jm] = u_s[rs][ty * 4 + jm][ip];
                #pragma unroll
                for (int jn = 0; jn < 5; jn++) ww[jn] = w_s[rs][ip][tx + 32 * jn];
                #pragma unroll
                for (int jm = 0; jm < 4; jm++)
                    #pragma unroll
                    for (int jn = 0; jn < 5; jn++)
                        fma2(acc[jm][jn], uu[jm], ww[jn]);
            }
        }
    }

    #pragma unroll
    for (int jm = 0; jm < 4; jm++) {
        int b = bt * BT + ty * 4 + jm;
        #pragma unroll
        for (int jn = 0; jn < 5; jn++) {
            int n = tx + 32 * jn;
            g_spart[(kb * BB + b) * NN + n] = lo2(acc[jm][jn]) + hi2(acc[jm][jn]);
        }
    }
}

// ---------------------------------------------------------------------------
// Reduce K-chunk partials, squash, write v (and final output).
// grid BB*NN/128, 128 threads
// ---------------------------------------------------------------------------
__global__ void reduce_squash_kernel(float* __restrict__ dout) {
    int idx = blockIdx.x * 128 + threadIdx.x;   // b*NN + n
    float s = 0.f;
    #pragma unroll
    for (int kb = 0; kb < NKB; kb++) s += g_spart[kb * BB * NN + idx];
    float sq = s * s;
    float out = sq / (1.f + sq) * s / (sqrtf(sq) + 1e-5f);
    g_v[idx] = out;
    dout[idx] = out;
}

// ---------------------------------------------------------------------------
// bT[c*16+d][r] += (1/B) sum_b t[c][b][r] * v[b, c*16+d]
// grid (RR/128, CC), 128 threads (one r per thread)
// ---------------------------------------------------------------------------
__global__ __launch_bounds__(128) void update_kernel(int first) {
    __shared__ u64 v_s[BB][DD / 2];   // 16 KB
    const int c = blockIdx.y;
    const int r = blockIdx.x * 128 + threadIdx.x;

    // stage v[:, c, :] — 1024 float4, 8 per thread
    #pragma unroll
    for (int k = 0; k < 8; k++) {
        int idx = threadIdx.x + 128 * k;   // 0..1023
        int b = idx >> 2, q = idx & 3;
        const float4 v4 = *(const float4*)(g_v + b * NN + c * DD + q * 4);
        v_s[b][q * 2 + 0] = pack2(v4.x, v4.y);
        v_s[b][q * 2 + 1] = pack2(v4.z, v4.w);
    }
    __syncthreads();

    const u64 z = pack2(0.f, 0.f);
    u64 acc[8];
    #pragma unroll
    for (int j = 0; j < 8; j++) acc[j] = z;

    const float* tp = g_t + (c * BB) * RR + r;
    for (int b0 = 0; b0 < BB; b0 += 8) {
        float tv[8];
        #pragma unroll
        for (int q = 0; q < 8; q++) tv[q] = tp[(b0 + q) * RR];
        #pragma unroll
        for (int q = 0; q < 8; q++) {
            u64 t2 = pack2(tv[q], tv[q]);
            #pragma unroll
            for (int j = 0; j < 8; j++) fma2(acc[j], t2, v_s[b0 + q][j]);
        }
    }

    const float inv = 1.f / (float)BB;
    #pragma unroll
    for (int j = 0; j < 8; j++) {
        float x = lo2(acc[j]) * inv;
        float y = hi2(acc[j]) * inv;
        int o0 = (c * DD + 2 * j) * RR + r;       // transposed, coalesced over r
        int o1 = (c * DD + 2 * j + 1) * RR + r;
        if (!first) { x += g_bT[o0]; y += g_bT[o1]; }
        g_bT[o0] = x;
        g_bT[o1] = y;
    }
}

// ---------------------------------------------------------------------------
// c[r,n] = softmax over r of bT[n][r].  grid NN blocks, 128 threads.
// Coalesced reads from bT; scattered (cheap) stores into g_c[r][n].
// ---------------------------------------------------------------------------
__global__ __launch_bounds__(128) void softmax_kernel() {
    __shared__ float red[128];
    const int n = blockIdx.x;
    const int tid = threadIdx.x;
    const float* bp = g_bT + n * RR;

    float vals[9];
    #pragma unroll
    for (int j = 0; j < 9; j++) vals[j] = bp[tid + 128 * j];

    float m = vals[0];
    #pragma unroll
    for (int j = 1; j < 9; j++) m = fmaxf(m, vals[j]);
    red[tid] = m;
    __syncthreads();
    for (int s = 64; s > 0; s >>= 1) {
        if (tid < s) red[tid] = fmaxf(red[tid], red[tid + s]);
        __syncthreads();
    }
    m = red[0];
    __syncthreads();

    float e[9];
    float lsum = 0.f;
    #pragma unroll
    for (int j = 0; j < 9; j++) { e[j] = expf(vals[j] - m); lsum += e[j]; }
    red[tid] = lsum;
    __syncthreads();
    for (int s = 64; s > 0; s >>= 1) {
        if (tid < s) red[tid] += red[tid + s];
        __syncthreads();
    }
    float inv = 1.f / red[0];

    #pragma unroll
    for (int j = 0; j < 9; j++)
        g_c[(tid + 128 * j) * NN + n] = e[j] * inv;
}

// ---------------------------------------------------------------------------
extern "C" void kernel_launch(void* const* d_in, const int* in_sizes, int n_in,
                              void* d_out, int out_size) {
    const float* u = (const float*)d_in[0];   // (B, R, 8)
    const float* W = (const float*)d_in[1];   // (R, C, 16, 8)
    float* out = (float*)d_out;               // (B, C, 16) = 40960 floats

    // Precompute (iteration-invariant)
    wsum_kernel<<<(RR * CC * II + 255) / 256, 256>>>(W);
    t_kernel<<<dim3(RR / 128, BB / BTB), 128>>>(u);

    // Iteration 0: c_ij uniform = 1/R
    gemm_kernel<<<dim3(NBT, NKB), 256>>>(u, W, 0, 1.0f / (float)RR);
    reduce_squash_kernel<<<BB * NN / 128, 128>>>(out);
    update_kernel<<<dim3(RR / 128, CC), 128>>>(1);
    softmax_kernel<<<NN, 128>>>();

    // Iteration 1
    gemm_kernel<<<dim3(NBT, NKB), 256>>>(u, W, 1, 0.f);
    reduce_squash_kernel<<<BB * NN / 128, 128>>>(out);
    update_kernel<<<dim3(RR / 128, CC), 128>>>(0);
    softmax_kernel<<<NN, 128>>>();

    // Iteration 2 (final v -> out)
    gemm_kernel<<<dim3(NBT, NKB), 256>>>(u, W, 1, 0.f);
    reduce_squash_kernel<<<BB * NN / 128, 128>>>(out);
}

// round 7
// speedup vs baseline: 1.4574x; 1.0506x over previous
#include <cuda_runtime.h>

// Problem constants
#define BB 256      // batch
#define RR 1152     // routes
#define CC 10       // caps
#define DD 16       // d_out
#define II 8        // d_in
#define NN 160      // CC*DD

// GEMM tiling
#define BT 64            // batch tile per block
#define RCHUNK 32        // routes per block (K split)
#define NKB 36           // RR / RCHUNK
#define NBT 4            // BB / BT
#define NSTAGE (RCHUNK/4)
#define GT 512           // gemm threads

#define BTB 8            // batch tile in t_kernel

typedef unsigned long long u64;

// Scratch (static device arrays; no allocation anywhere)
__device__ float g_wsumT[CC * II * RR];       // [c][i][r] sum_d W[r,c,d,i]
__device__ float g_t[CC * BB * RR];           // t[c][b][r] = sum_d u_hat
__device__ float g_spart[NKB * BB * NN];      // per-K-chunk partial s
__device__ float g_v[BB * NN];                // squashed v
__device__ float g_bT[NN * RR];               // routing logits, transposed [n][r]
__device__ float g_c[RR * NN];                // softmax(b) over r, [r][n]

// ---- packed f32x2 helpers (FFMA2 path on sm_103a) ----
__device__ __forceinline__ u64 pack2(float lo, float hi) {
    u64 r;
    asm("mov.b64 %0, {%1, %2};" : "=l"(r) : "f"(lo), "f"(hi));
    return r;
}
__device__ __forceinline__ float lo2(u64 v) { return __uint_as_float((unsigned int)v); }
__device__ __forceinline__ float hi2(u64 v) { return __uint_as_float((unsigned int)(v >> 32)); }
__device__ __forceinline__ void fma2(u64& d, u64 a, u64 b) {
    asm("fma.rn.f32x2 %0, %1, %2, %0;" : "+l"(d) : "l"(a), "l"(b));
}

// ---------------------------------------------------------------------------
// wsumT[c][i][r] = sum_d W[r,c,d,i]
// ---------------------------------------------------------------------------
__global__ void wsum_kernel(const float* __restrict__ W) {
    int id = blockIdx.x * blockDim.x + threadIdx.x;   // over RR*CC*II
    if (id >= RR * CC * II) return;
    int rc = id / II, i = id - rc * II;
    int r = rc / CC, c = rc - r * CC;
    const float* p = W + rc * DD * II + i;
    float s = 0.f;
    #pragma unroll
    for (int d = 0; d < DD; d++) s += p[d * II];
    g_wsumT[(c * II + i) * RR + r] = s;
}

// ---------------------------------------------------------------------------
// t[c][b][r] = sum_i wsumT[c][i][r] * u[b,r,i]   (iteration-invariant)
// ---------------------------------------------------------------------------
__global__ __launch_bounds__(128) void t_kernel(const float* __restrict__ u) {
    const int r = blockIdx.x * 128 + threadIdx.x;
    const int b0 = blockIdx.y * BTB;

    float uu[BTB][II];
    #pragma unroll
    for (int bi = 0; bi < BTB; bi++) {
        const float4* up = (const float4*)(u + ((b0 + bi) * RR + r) * II);
        float4 a = up[0], b = up[1];
        uu[bi][0] = a.x; uu[bi][1] = a.y; uu[bi][2] = a.z; uu[bi][3] = a.w;
        uu[bi][4] = b.x; uu[bi][5] = b.y; uu[bi][6] = b.z; uu[bi][7] = b.w;
    }

    #pragma unroll
    for (int c = 0; c < CC; c++) {
        float ws[II];
        #pragma unroll
        for (int i = 0; i < II; i++) ws[i] = g_wsumT[(c * II + i) * RR + r];
        #pragma unroll
        for (int bi = 0; bi < BTB; bi++) {
            float s = 0.f;
            #pragma unroll
            for (int i = 0; i < II; i++) s += ws[i] * uu[bi][i];
            g_t[(c * BB + b0 + bi) * RR + r] = s;
        }
    }
}

// ---------------------------------------------------------------------------
// s_part[kb][b][n] = sum_{r in chunk kb} c[r,n] * sum_i W[r,n,i]*u[b,r,i]
// 512 threads, 64-batch tile (W tile shared 2x wider -> half L2 traffic).
// thread = (ty 0..15, tx 0..31): 4 b's x 5 n's, FFMA2 over paired i.
// ---------------------------------------------------------------------------
__global__ __launch_bounds__(GT, 1) void gemm_kernel(
    const float* __restrict__ u, const float* __restrict__ W,
    int use_c, float cuni)
{
    __shared__ u64 u_s[4][BT][4];   // [rs][m][ip]  8 KB
    __shared__ u64 w_s[4][4][NN];   // [rs][ip][n]  20 KB

    const int tid = threadIdx.x;
    const int tx = tid & 31, ty = tid >> 5;
    const int bt = blockIdx.x, kb = blockIdx.y;
    const int r0 = kb * RCHUNK;

    const u64 z = pack2(0.f, 0.f);
    u64 acc[4][5];
    #pragma unroll
    for (int jm = 0; jm < 4; jm++)
        #pragma unroll
        for (int jn = 0; jn < 5; jn++) acc[jm][jn] = z;

    // staging index decomposition (stage-invariant)
    const int sbl = tid & 63;          // b within tile
    const int srs = (tid >> 6) & 3;    // r within 4-row stage
    const int shalf = tid >> 8;        // i half
    int wrs[3], wn[3], wiq[3];
    bool wok[3];
    #pragma unroll
    for (int k = 0; k < 3; k++) {
        int idx = tid + GT * k;          // 0..1535, valid < 1280
        wok[k] = idx < 1280;
        int i2 = wok[k] ? idx : 0;
        wrs[k] = i2 / 320;
        int rem = i2 - wrs[k] * 320;
        wn[k] = rem >> 1;
        wiq[k] = rem & 1;
    }

    // prefetch registers
    float4 pu;
    float4 pw[3];
    float  pc[3];

    // prologue: prefetch stage 0
    {
        pu = *(const float4*)(u + ((bt * BT + sbl) * RR + r0 + srs) * II + shalf * 4);
        #pragma unroll
        for (int k = 0; k < 3; k++) {
            if (wok[k]) {
                int r = r0 + wrs[k];
                pc[k] = use_c ? g_c[r * NN + wn[k]] : cuni;
                pw[k] = *(const float4*)(W + (r * NN + wn[k]) * II + wiq[k] * 4);
            }
        }
    }

    for (int st = 0; st < NSTAGE; st++) {
        if (st) __syncthreads();          // prev compute done reading smem

        // commit prefetched tile to smem (fold c into W)
        u_s[srs][sbl][shalf * 2 + 0] = pack2(pu.x, pu.y);
        u_s[srs][sbl][shalf * 2 + 1] = pack2(pu.z, pu.w);
        #pragma unroll
        for (int k = 0; k < 3; k++) {
            if (wok[k]) {
                w_s[wrs[k]][wiq[k] * 2 + 0][wn[k]] = pack2(pw[k].x * pc[k], pw[k].y * pc[k]);
                w_s[wrs[k]][wiq[k] * 2 + 1][wn[k]] = pack2(pw[k].z * pc[k], pw[k].w * pc[k]);
            }
        }

        // prefetch next stage (overlaps with compute below)
        if (st < NSTAGE - 1) {
            const int rb = r0 + (st + 1) * 4;
            pu = *(const float4*)(u + ((bt * BT + sbl) * RR + rb + srs) * II + shalf * 4);
            #pragma unroll
            for (int k = 0; k < 3; k++) {
                if (wok[k]) {
                    int r = rb + wrs[k];
                    pc[k] = use_c ? g_c[r * NN + wn[k]] : cuni;
                    pw[k] = *(const float4*)(W + (r * NN + wn[k]) * II + wiq[k] * 4);
                }
            }
        }
        __syncthreads();

        #pragma unroll
        for (int rs = 0; rs < 4; rs++) {
            #pragma unroll
            for (int ip = 0; ip < 4; ip++) {
                u64 uu[4], ww[5];
                #pragma unroll
                for (int jm = 0; jm < 4; jm++) uu[jm] = u_s[rs][ty * 4 + jm][ip];
                #pragma unroll
                for (int jn = 0; jn < 5; jn++) ww[jn] = w_s[rs][ip][tx + 32 * jn];
                #pragma unroll
                for (int jm = 0; jm < 4; jm++)
                    #pragma unroll
                    for (int jn = 0; jn < 5; jn++)
                        fma2(acc[jm][jn], uu[jm], ww[jn]);
            }
        }
    }

    #pragma unroll
    for (int jm = 0; jm < 4; jm++) {
        int b = bt * BT + ty * 4 + jm;
        #pragma unroll
        for (int jn = 0; jn < 5; jn++) {
            int n = tx + 32 * jn;
            g_spart[(kb * BB + b) * NN + n] = lo2(acc[jm][jn]) + hi2(acc[jm][jn]);
        }
    }
}

// ---------------------------------------------------------------------------
// Reduce K-chunk partials (float4, 4 indep accumulators), squash, write v.
// grid = BB*NN/(128*4) = 80 blocks, 128 threads; each thread 4 floats.
// ---------------------------------------------------------------------------
__global__ __launch_bounds__(128) void reduce_squash_kernel(float* __restrict__ dout) {
    const int idx4 = blockIdx.x * 128 + threadIdx.x;   // over BB*NN/4 = 10240
    const float4* sp = (const float4*)g_spart;
    const int stride4 = BB * NN / 4;                   // 10240

    float4 a0 = make_float4(0.f, 0.f, 0.f, 0.f);
    float4 a1 = a0, a2 = a0, a3 = a0;
    #pragma unroll
    for (int kb = 0; kb < NKB; kb += 4) {
        float4 x0 = sp[(kb + 0) * stride4 + idx4];
        float4 x1 = sp[(kb + 1) * stride4 + idx4];
        float4 x2 = sp[(kb + 2) * stride4 + idx4];
        float4 x3 = sp[(kb + 3) * stride4 + idx4];
        a0.x += x0.x; a0.y += x0.y; a0.z += x0.z; a0.w += x0.w;
        a1.x += x1.x; a1.y += x1.y; a1.z += x1.z; a1.w += x1.w;
        a2.x += x2.x; a2.y += x2.y; a2.z += x2.z; a2.w += x2.w;
        a3.x += x3.x; a3.y += x3.y; a3.z += x3.z; a3.w += x3.w;
    }
    float s[4];
    s[0] = (a0.x + a1.x) + (a2.x + a3.x);
    s[1] = (a0.y + a1.y) + (a2.y + a3.y);
    s[2] = (a0.z + a1.z) + (a2.z + a3.z);
    s[3] = (a0.w + a1.w) + (a2.w + a3.w);

    float4 o;
    float* op = &o.x;
    #pragma unroll
    for (int q = 0; q < 4; q++) {
        float sq = s[q] * s[q];
        op[q] = sq / (1.f + sq) * s[q] / (sqrtf(sq) + 1e-5f);
    }
    ((float4*)g_v)[idx4] = o;
    ((float4*)dout)[idx4] = o;
}

// ---------------------------------------------------------------------------
// bT[c*16+d][r] += (1/B) sum_b t[c][b][r] * v[b, c*16+d]
// ---------------------------------------------------------------------------
__global__ __launch_bounds__(128) void update_kernel(int first) {
    __shared__ u64 v_s[BB][DD / 2];   // 16 KB
    const int c = blockIdx.y;
    const int r = blockIdx.x * 128 + threadIdx.x;

    #pragma unroll
    for (int k = 0; k < 8; k++) {
        int idx = threadIdx.x + 128 * k;   // 0..1023
        int b = idx >> 2, q = idx & 3;
        const float4 v4 = *(const float4*)(g_v + b * NN + c * DD + q * 4);
        v_s[b][q * 2 + 0] = pack2(v4.x, v4.y);
        v_s[b][q * 2 + 1] = pack2(v4.z, v4.w);
    }
    __syncthreads();

    const u64 z = pack2(0.f, 0.f);
    u64 acc[8];
    #pragma unroll
    for (int j = 0; j < 8; j++) acc[j] = z;

    const float* tp = g_t + (c * BB) * RR + r;
    for (int b0 = 0; b0 < BB; b0 += 8) {
        float tv[8];
        #pragma unroll
        for (int q = 0; q < 8; q++) tv[q] = tp[(b0 + q) * RR];
        #pragma unroll
        for (int q = 0; q < 8; q++) {
            u64 t2 = pack2(tv[q], tv[q]);
            #pragma unroll
            for (int j = 0; j < 8; j++) fma2(acc[j], t2, v_s[b0 + q][j]);
        }
    }

    const float inv = 1.f / (float)BB;
    #pragma unroll
    for (int j = 0; j < 8; j++) {
        float x = lo2(acc[j]) * inv;
        float y = hi2(acc[j]) * inv;
        int o0 = (c * DD + 2 * j) * RR + r;
        int o1 = (c * DD + 2 * j + 1) * RR + r;
        if (!first) { x += g_bT[o0]; y += g_bT[o1]; }
        g_bT[o0] = x;
        g_bT[o1] = y;
    }
}

// ---------------------------------------------------------------------------
// c[r,n] = softmax over r of bT[n][r].
// ---------------------------------------------------------------------------
__global__ __launch_bounds__(128) void softmax_kernel() {
    __shared__ float red[128];
    const int n = blockIdx.x;
    const int tid = threadIdx.x;
    const float* bp = g_bT + n * RR;

    float vals[9];
    #pragma unroll
    for (int j = 0; j < 9; j++) vals[j] = bp[tid + 128 * j];

    float m = vals[0];
    #pragma unroll
    for (int j = 1; j < 9; j++) m = fmaxf(m, vals[j]);
    red[tid] = m;
    __syncthreads();
    for (int s = 64; s > 0; s >>= 1) {
        if (tid < s) red[tid] = fmaxf(red[tid], red[tid + s]);
        __syncthreads();
    }
    m = red[0];
    __syncthreads();

    float e[9];
    float lsum = 0.f;
    #pragma unroll
    for (int j = 0; j < 9; j++) { e[j] = expf(vals[j] - m); lsum += e[j]; }
    red[tid] = lsum;
    __syncthreads();
    for (int s = 64; s > 0; s >>= 1) {
        if (tid < s) red[tid] += red[tid + s];
        __syncthreads();
    }
    float inv = 1.f / red[0];

    #pragma unroll
    for (int j = 0; j < 9; j++)
        g_c[(tid + 128 * j) * NN + n] = e[j] * inv;
}

// ---------------------------------------------------------------------------
extern "C" void kernel_launch(void* const* d_in, const int* in_sizes, int n_in,
                              void* d_out, int out_size) {
    const float* u = (const float*)d_in[0];   // (B, R, 8)
    const float* W = (const float*)d_in[1];   // (R, C, 16, 8)
    float* out = (float*)d_out;               // (B, C, 16) = 40960 floats

    wsum_kernel<<<(RR * CC * II + 255) / 256, 256>>>(W);
    t_kernel<<<dim3(RR / 128, BB / BTB), 128>>>(u);

    // Iteration 0: c_ij uniform = 1/R
    gemm_kernel<<<dim3(NBT, NKB), GT>>>(u, W, 0, 1.0f / (float)RR);
    reduce_squash_kernel<<<BB * NN / 512, 128>>>(out);
    update_kernel<<<dim3(RR / 128, CC), 128>>>(1);
    softmax_kernel<<<NN, 128>>>();

    // Iteration 1
    gemm_kernel<<<dim3(NBT, NKB), GT>>>(u, W, 1, 0.f);
    reduce_squash_kernel<<<BB * NN / 512, 128>>>(out);
    update_kernel<<<dim3(RR / 128, CC), 128>>>(0);
    softmax_kernel<<<NN, 128>>>();

    // Iteration 2 (final v -> out)
    gemm_kernel<<<dim3(NBT, NKB), GT>>>(u, W, 1, 0.f);
    reduce_squash_kernel<<<BB * NN / 512, 128>>>(out);
}